// round 13
// baseline (speedup 1.0000x reference)
#include <cuda_runtime.h>
#include <cstdint>

// Problem constants
#define DD    256
#define HW    4096
#define NTOK  65536          // 16 * 4096
#define KCB   2048
#define QSIZE 16777216       // 16 * 256 * 4096
// out layout (float32): [0..QSIZE) q, [QSIZE] loss, [QSIZE+1] codebook_loss,
// [QSIZE+2] commitment_loss, [QSIZE+3 .. +KCB) counts

#define EPS_SEL 1.25e-2f
#define CAND    40

// Scratch (device globals — no allocs allowed)
__device__ float    g_c2[KCB];
__device__ float    g_csc[KCB];              // cmax/127 (reconstruct scale)
__device__ float    g_z2[NTOK];
__device__ float    g_zsc[NTOK];             // zmax/127
__device__ float    g_zt[(size_t)NTOK * DD]; // z fp32 token-major (64 MB)
__device__ uint32_t g_qzp[64u * NTOK];       // z int8 quads, plane-major (16 MB)
__device__ uint32_t g_qc[(size_t)KCB * 64];  // codebook int8 quads (512 KB)
__device__ int      g_ccnt[NTOK];
__device__ int      g_cand[(size_t)NTOK * CAND];
__device__ int      g_idx[NTOK];

// ---------------------------------------------------------------------------
__device__ __forceinline__ uint32_t ordf(float s) {
    uint32_t u = __float_as_uint(s);
    return (u & 0x80000000u) ? ~u : (u | 0x80000000u);
}
__device__ __forceinline__ float unordf(uint32_t u) {
    return __uint_as_float((u & 0x80000000u) ? (u & 0x7fffffffu) : ~u);
}
__device__ __forceinline__ uint32_t pack4(float a, float b, float c, float d,
                                          float inv) {
    int q0 = max(-127, min(127, __float2int_rn(a * inv)));
    int q1 = max(-127, min(127, __float2int_rn(b * inv)));
    int q2 = max(-127, min(127, __float2int_rn(c * inv)));
    int q3 = max(-127, min(127, __float2int_rn(d * inv)));
    return (uint32_t)(q0 & 255) | ((uint32_t)(q1 & 255) << 8) |
           ((uint32_t)(q2 & 255) << 16) | ((uint32_t)q3 << 24);
}

// exact fp32 rescore — byte-identical to round 7 (validated at 2.384798e-07)
__device__ __forceinline__ unsigned long long rescore(int n, int k,
                                                      const float* __restrict__ cb) {
    const float4* zp = (const float4*)(g_zt + (size_t)n * DD);
    const float4* cr = (const float4*)(cb + (size_t)k * DD);
    float s0 = 0.f, s1 = 0.f, s2 = 0.f, s3 = 0.f;
    #pragma unroll 8
    for (int i = 0; i < 64; i++) {
        float4 a = zp[i], b = cr[i];
        s0 = fmaf(a.x, b.x, s0); s1 = fmaf(a.y, b.y, s1);
        s2 = fmaf(a.z, b.z, s2); s3 = fmaf(a.w, b.w, s3);
    }
    float dot  = (s0 + s1) + (s2 + s3);
    float dist = fmaf(-2.0f, dot, g_z2[n] + g_c2[k]);
    return ((unsigned long long)__float_as_uint(dist) << 32) | (unsigned)k;
}

// ---------------------------------------------------------------------------
__global__ void init_kernel(float* out) {
    int i = threadIdx.x + blockIdx.x * blockDim.x;
    if (i < 3 + KCB) out[QSIZE + i] = 0.0f;
    if (i < NTOK) g_ccnt[i] = 0;
}

// c2 + per-code max (one warp per code)
__global__ void c2_kernel(const float* __restrict__ cb) {
    int warp = (threadIdx.x >> 5) + blockIdx.x * (blockDim.x >> 5);
    int lane = threadIdx.x & 31;
    if (warp >= KCB) return;
    const float* row = cb + (size_t)warp * DD;
    float s = 0.f, mx = 0.f;
    #pragma unroll
    for (int d = lane; d < DD; d += 32) {
        float v = row[d];
        s = fmaf(v, v, s);
        mx = fmaxf(mx, fabsf(v));
    }
    #pragma unroll
    for (int off = 16; off; off >>= 1) {
        s += __shfl_down_sync(0xffffffffu, s, off);
        mx = fmaxf(mx, __shfl_down_sync(0xffffffffu, mx, off));
    }
    if (lane == 0) {
        g_c2[warp]  = s;
        g_csc[warp] = (mx > 0.f) ? mx * (1.0f / 127.0f) : 1.0f;
    }
}

// z2 + per-token max (sequential fp32 sum preserved for z2)
__global__ void z2_kernel(const float* __restrict__ z) {
    int n = threadIdx.x + blockIdx.x * blockDim.x;
    if (n >= NTOK) return;
    int b = n >> 12, hw = n & 4095;
    const float* p = z + (size_t)b * (DD * HW) + hw;
    float s = 0.f, mx = 0.f;
    #pragma unroll 8
    for (int d = 0; d < DD; d++) {
        float v = p[(size_t)d * HW];
        s = fmaf(v, v, s);
        mx = fmaxf(mx, fabsf(v));
    }
    g_z2[n]  = s;
    g_zsc[n] = (mx > 0.f) ? mx * (1.0f / 127.0f) : 1.0f;
}

// transpose z -> token-major fp32 (for exact rescore + quantization source)
__global__ __launch_bounds__(256)
void tz_kernel(const float* __restrict__ z) {
    __shared__ float t[64][65];
    const int bx = blockIdx.x;
    const int hw0 = (bx & 63) * 64;
    const int d0  = ((bx >> 6) & 3) * 64;
    const int b   = bx >> 8;
    const float* zb = z + (size_t)b * (DD * HW);
    const int tid = threadIdx.x;
    #pragma unroll
    for (int it = 0; it < 16; it++) {
        int p = tid + it * 256;
        int dd = p >> 6, r = p & 63;
        t[dd][r] = zb[(size_t)(d0 + dd) * HW + hw0 + r];
    }
    __syncthreads();
    #pragma unroll
    for (int it = 0; it < 16; it++) {
        int p = tid + it * 256;
        int r = p >> 6, dd = p & 63;
        size_t n = (size_t)b * 4096 + hw0 + r;
        g_zt[n * 256 + d0 + dd] = t[dd][r];
    }
}

// quantize z -> int8 quad planes g_qzp[dq][n]
__global__ void qz_kernel() {
    int idx = threadIdx.x + blockIdx.x * blockDim.x;   // 64 * 65536
    int dq = idx >> 16, n = idx & 65535;
    float inv = 127.0f * __frcp_rn(g_zsc[n] * 127.0f);  // == 1/zsc
    const float4 v = *(const float4*)(g_zt + (size_t)n * 256 + dq * 4);
    g_qzp[(size_t)dq * NTOK + n] = pack4(v.x, v.y, v.z, v.w, inv);
}

// quantize codebook -> int8 quads g_qc[k][64]
__global__ void qc_kernel(const float* __restrict__ cb) {
    int idx = threadIdx.x + blockIdx.x * blockDim.x;   // 2048 * 64
    if (idx >= KCB * 64) return;
    int k = idx >> 6, dq = idx & 63;
    float inv = 127.0f * __frcp_rn(g_csc[k] * 127.0f);
    const float4 v = *(const float4*)(cb + (size_t)k * 256 + dq * 4);
    g_qc[idx] = pack4(v.x, v.y, v.z, v.w, inv);
}

// ---------------------------------------------------------------------------
// Filter kernel: 128 tokens/CTA x 2048 codes via DP4A (exact int32 acc);
// shared per-token running min + candidate append. No calls, no spills.
// ---------------------------------------------------------------------------
__global__ __launch_bounds__(256, 2)
void vq_filter_kernel() {
    __shared__ uint32_t As[8][128];          // [dq][token] int8 quads
    __shared__ uint32_t Bs[8][132];          // [dq][code]
    __shared__ uint32_t sm_m[128];           // per-token shared min (ordered)

    const int tid = threadIdx.x;
    const int tx = tid & 15;
    const int ty = tid >> 4;
    const int n0 = blockIdx.x * 128;

    if (tid < 128) sm_m[tid] = 0xFFFFFFFFu;

    float m_loc[8], zs2[8];
    #pragma unroll
    for (int i = 0; i < 8; i++) {
        m_loc[i] = __int_as_float(0x7f800000);
        zs2[i] = 2.0f * g_zsc[n0 + ty + 16 * i];
    }

    const int a_dq = tid >> 5;
    const int a_tq = (tid & 31) * 4;
    const int b_kk = tid >> 1;
    const int b_p  = (tid & 1) * 4;

    for (int kc = 0; kc < KCB; kc += 128) {
        int acc[8][8];
        #pragma unroll
        for (int i = 0; i < 8; i++)
            #pragma unroll
            for (int j = 0; j < 8; j++) acc[i][j] = 0;

        for (int dq0 = 0; dq0 < 64; dq0 += 8) {
            uint4 av = *(const uint4*)(g_qzp + (size_t)(dq0 + a_dq) * NTOK + n0 + a_tq);
            uint4 bv = *(const uint4*)(g_qc + (size_t)(kc + b_kk) * 64 + dq0 + b_p);
            __syncthreads();
            *(uint4*)&As[a_dq][a_tq] = av;
            Bs[b_p + 0][b_kk] = bv.x;
            Bs[b_p + 1][b_kk] = bv.y;
            Bs[b_p + 2][b_kk] = bv.z;
            Bs[b_p + 3][b_kk] = bv.w;
            __syncthreads();

            #pragma unroll
            for (int dq = 0; dq < 8; dq++) {
                uint32_t a[8], b[8];
                #pragma unroll
                for (int i = 0; i < 8; i++) a[i] = As[dq][ty + 16 * i];
                #pragma unroll
                for (int j = 0; j < 8; j++) b[j] = Bs[dq][tx + 16 * j];
                #pragma unroll
                for (int i = 0; i < 8; i++)
                    #pragma unroll
                    for (int j = 0; j < 8; j++)
                        acc[i][j] = __dp4a((int)a[i], (int)b[j], acc[i][j]);
            }
        }

        // scan: approx score, shared-min update, candidate append
        #pragma unroll
        for (int j = 0; j < 8; j++) {
            const int k = kc + tx + 16 * j;
            const float cs  = g_csc[k];
            const float c2k = g_c2[k];
            #pragma unroll
            for (int i = 0; i < 8; i++) {
                float s = fmaf(-zs2[i] * cs, (float)acc[i][j], c2k);
                if (s < m_loc[i]) {
                    m_loc[i] = s;
                    atomicMin(&sm_m[ty + 16 * i], ordf(s));
                }
                if (s <= m_loc[i] + EPS_SEL) {
                    float msh = unordf(sm_m[ty + 16 * i]);
                    if (s <= msh + EPS_SEL) {
                        int n = n0 + ty + 16 * i;
                        int slot = atomicAdd(&g_ccnt[n], 1);
                        if (slot < CAND) g_cand[(size_t)n * CAND + slot] = k;
                    }
                }
            }
        }
    }
}

// ---------------------------------------------------------------------------
// Rescore kernel: one warp per token; exact fp32 dist (round-7 formula),
// (bits<<32)|k min => first-index tie-break. Overflow -> full scan.
// ---------------------------------------------------------------------------
__global__ __launch_bounds__(256)
void vq_rescore_kernel(const float* __restrict__ cb) {
    const int lane = threadIdx.x & 31;
    const int n = blockIdx.x * 8 + (threadIdx.x >> 5);
    const int cnt = g_ccnt[n];

    unsigned long long key = ~0ULL;
    if (cnt <= CAND) {
        for (int c = lane; c < cnt; c += 32) {
            unsigned long long x = rescore(n, g_cand[(size_t)n * CAND + c], cb);
            if (x < key) key = x;
        }
    } else {
        for (int k = lane; k < KCB; k += 32) {
            unsigned long long x = rescore(n, k, cb);
            if (x < key) key = x;
        }
    }
    #pragma unroll
    for (int off = 16; off; off >>= 1) {
        unsigned long long x = __shfl_xor_sync(0xffffffffu, key, off);
        if (x < key) key = x;
    }
    if (lane == 0) g_idx[n] = (int)(key & 0xFFFFFFFFu);
}

// ---------------------------------------------------------------------------
// Output epilogue: q (straight-through), counts, fused SSE
// ---------------------------------------------------------------------------
__global__ __launch_bounds__(256)
void vq_out_kernel(const float* __restrict__ z, const float* __restrict__ cb,
                   float* __restrict__ out) {
    __shared__ float lred[8];
    const int tid = threadIdx.x;
    const int n0 = blockIdx.x * 128;
    const int b = n0 >> 12, hw0 = n0 & 4095;

    if (tid < 128) atomicAdd(out + QSIZE + 3 + g_idx[n0 + tid], 1.0f);

    const int tok  = tid & 127;
    const int half = tid >> 7;
    const int kidx = g_idx[n0 + tok];
    const float* crow = cb + (size_t)kidx * DD;
    float* qbase = out + (size_t)b * (DD * HW) + hw0 + tok;
    const float* zb2 = z + (size_t)b * (DD * HW) + hw0 + tok;
    float lsum = 0.f;
    #pragma unroll 4
    for (int d = half * 128; d < half * 128 + 128; d++) {
        float c  = crow[d];
        float zz = zb2[(size_t)d * HW];
        float df = zz - c;
        lsum = fmaf(df, df, lsum);
        qbase[(size_t)d * HW] = zz + (c - zz);   // == reference ST rounding
    }
    #pragma unroll
    for (int off = 16; off; off >>= 1) lsum += __shfl_down_sync(0xffffffffu, lsum, off);
    if ((tid & 31) == 0) lred[tid >> 5] = lsum;
    __syncthreads();
    if (tid == 0) {
        float s = 0.f;
        #pragma unroll
        for (int w = 0; w < 8; w++) s += lred[w];
        atomicAdd(out + QSIZE + 1, s);
    }
}

__global__ void finalize_kernel(float* out) {
    float sse = out[QSIZE + 1];
    float mse = sse / (float)((size_t)NTOK * DD);
    out[QSIZE]     = fmaf(0.25f, mse, mse);
    out[QSIZE + 1] = mse;
    out[QSIZE + 2] = mse;
}

// ---------------------------------------------------------------------------
extern "C" void kernel_launch(void* const* d_in, const int* in_sizes, int n_in,
                              void* d_out, int out_size) {
    const float* z  = (const float*)d_in[0];     // (16, 256, 64, 64)
    const float* cb = (const float*)d_in[1];     // (2048, 256)
    float* out = (float*)d_out;

    init_kernel<<<NTOK / 256 + 9, 256>>>(out);
    c2_kernel<<<KCB / 8, 256>>>(cb);
    z2_kernel<<<NTOK / 256, 256>>>(z);
    tz_kernel<<<4096, 256>>>(z);
    qz_kernel<<<64 * NTOK / 256, 256>>>();
    qc_kernel<<<KCB * 64 / 256, 256>>>(cb);
    vq_filter_kernel<<<NTOK / 128, 256>>>();
    vq_rescore_kernel<<<NTOK / 8, 256>>>(cb);
    vq_out_kernel<<<NTOK / 128, 256>>>(z, cb, out);
    finalize_kernel<<<1, 1>>>(out);
}

// round 14
// speedup vs baseline: 1.6451x; 1.6451x over previous
#include <cuda_runtime.h>
#include <cstdint>

// Problem constants
#define DD    256
#define HW    4096
#define NTOK  65536          // 16 * 4096
#define KCB   2048
#define QSIZE 16777216       // 16 * 256 * 4096
// out layout (float32): [0..QSIZE) q, [QSIZE] loss, [QSIZE+1] codebook_loss,
// [QSIZE+2] commitment_loss, [QSIZE+3 .. +KCB) counts

#define EPS_SEL 1.25e-2f
#define CAND    40

// Scratch (device globals — no allocs allowed)
__device__ float    g_c2[KCB];
__device__ float    g_csc[KCB];              // cmax/127 (reconstruct scale)
__device__ float    g_z2[NTOK];
__device__ float    g_zsc[NTOK];             // zmax/127
__device__ float    g_zt[(size_t)NTOK * DD]; // z fp32 token-major (64 MB)
__device__ uint32_t g_qzp[64u * NTOK];       // z int8 quads, plane-major (16 MB)
__device__ uint32_t g_qc[(size_t)KCB * 64];  // codebook int8 quads (512 KB)
__device__ int      g_ccnt[NTOK];
__device__ int      g_cand[(size_t)NTOK * CAND];
__device__ int      g_idx[NTOK];

// ---------------------------------------------------------------------------
__device__ __forceinline__ uint32_t ordf(float s) {
    uint32_t u = __float_as_uint(s);
    return (u & 0x80000000u) ? ~u : (u | 0x80000000u);
}
__device__ __forceinline__ float unordf(uint32_t u) {
    return __uint_as_float((u & 0x80000000u) ? (u & 0x7fffffffu) : ~u);
}
__device__ __forceinline__ uint32_t pack4(float a, float b, float c, float d,
                                          float inv) {
    int q0 = max(-127, min(127, __float2int_rn(a * inv)));
    int q1 = max(-127, min(127, __float2int_rn(b * inv)));
    int q2 = max(-127, min(127, __float2int_rn(c * inv)));
    int q3 = max(-127, min(127, __float2int_rn(d * inv)));
    return (uint32_t)(q0 & 255) | ((uint32_t)(q1 & 255) << 8) |
           ((uint32_t)(q2 & 255) << 16) | ((uint32_t)q3 << 24);
}

// exact fp32 rescore — byte-identical to round 7 (validated at 2.384798e-07)
__device__ __forceinline__ unsigned long long rescore(int n, int k,
                                                      const float* __restrict__ cb) {
    const float4* zp = (const float4*)(g_zt + (size_t)n * DD);
    const float4* cr = (const float4*)(cb + (size_t)k * DD);
    float s0 = 0.f, s1 = 0.f, s2 = 0.f, s3 = 0.f;
    #pragma unroll 8
    for (int i = 0; i < 64; i++) {
        float4 a = zp[i], b = cr[i];
        s0 = fmaf(a.x, b.x, s0); s1 = fmaf(a.y, b.y, s1);
        s2 = fmaf(a.z, b.z, s2); s3 = fmaf(a.w, b.w, s3);
    }
    float dot  = (s0 + s1) + (s2 + s3);
    float dist = fmaf(-2.0f, dot, g_z2[n] + g_c2[k]);
    return ((unsigned long long)__float_as_uint(dist) << 32) | (unsigned)k;
}

// ---------------------------------------------------------------------------
__global__ void init_kernel(float* out) {
    int i = threadIdx.x + blockIdx.x * blockDim.x;
    if (i < 3 + KCB) out[QSIZE + i] = 0.0f;
    if (i < NTOK) g_ccnt[i] = 0;
}

// c2 + per-code max (one warp per code)
__global__ void c2_kernel(const float* __restrict__ cb) {
    int warp = (threadIdx.x >> 5) + blockIdx.x * (blockDim.x >> 5);
    int lane = threadIdx.x & 31;
    if (warp >= KCB) return;
    const float* row = cb + (size_t)warp * DD;
    float s = 0.f, mx = 0.f;
    #pragma unroll
    for (int d = lane; d < DD; d += 32) {
        float v = row[d];
        s = fmaf(v, v, s);
        mx = fmaxf(mx, fabsf(v));
    }
    #pragma unroll
    for (int off = 16; off; off >>= 1) {
        s += __shfl_down_sync(0xffffffffu, s, off);
        mx = fmaxf(mx, __shfl_down_sync(0xffffffffu, mx, off));
    }
    if (lane == 0) {
        g_c2[warp]  = s;
        g_csc[warp] = (mx > 0.f) ? mx * (1.0f / 127.0f) : 1.0f;
    }
}

// z2 + per-token max (sequential fp32 sum preserved for z2)
__global__ void z2_kernel(const float* __restrict__ z) {
    int n = threadIdx.x + blockIdx.x * blockDim.x;
    if (n >= NTOK) return;
    int b = n >> 12, hw = n & 4095;
    const float* p = z + (size_t)b * (DD * HW) + hw;
    float s = 0.f, mx = 0.f;
    #pragma unroll 8
    for (int d = 0; d < DD; d++) {
        float v = p[(size_t)d * HW];
        s = fmaf(v, v, s);
        mx = fmaxf(mx, fabsf(v));
    }
    g_z2[n]  = s;
    g_zsc[n] = (mx > 0.f) ? mx * (1.0f / 127.0f) : 1.0f;
}

// transpose z -> token-major fp32 (for exact rescore + quantization source)
__global__ __launch_bounds__(256)
void tz_kernel(const float* __restrict__ z) {
    __shared__ float t[64][65];
    const int bx = blockIdx.x;
    const int hw0 = (bx & 63) * 64;
    const int d0  = ((bx >> 6) & 3) * 64;
    const int b   = bx >> 8;
    const float* zb = z + (size_t)b * (DD * HW);
    const int tid = threadIdx.x;
    #pragma unroll
    for (int it = 0; it < 16; it++) {
        int p = tid + it * 256;
        int dd = p >> 6, r = p & 63;
        t[dd][r] = zb[(size_t)(d0 + dd) * HW + hw0 + r];
    }
    __syncthreads();
    #pragma unroll
    for (int it = 0; it < 16; it++) {
        int p = tid + it * 256;
        int r = p >> 6, dd = p & 63;
        size_t n = (size_t)b * 4096 + hw0 + r;
        g_zt[n * 256 + d0 + dd] = t[dd][r];
    }
}

// quantize z -> int8 quad planes g_qzp[dq][n]
__global__ void qz_kernel() {
    int idx = threadIdx.x + blockIdx.x * blockDim.x;   // 64 * 65536
    int dq = idx >> 16, n = idx & 65535;
    float inv = 127.0f * __frcp_rn(g_zsc[n] * 127.0f);  // == 1/zsc
    const float4 v = *(const float4*)(g_zt + (size_t)n * 256 + dq * 4);
    g_qzp[(size_t)dq * NTOK + n] = pack4(v.x, v.y, v.z, v.w, inv);
}

// quantize codebook -> int8 quads g_qc[k][64]
__global__ void qc_kernel(const float* __restrict__ cb) {
    int idx = threadIdx.x + blockIdx.x * blockDim.x;   // 2048 * 64
    if (idx >= KCB * 64) return;
    int k = idx >> 6, dq = idx & 63;
    float inv = 127.0f * __frcp_rn(g_csc[k] * 127.0f);
    const float4 v = *(const float4*)(cb + (size_t)k * 256 + dq * 4);
    g_qc[idx] = pack4(v.x, v.y, v.z, v.w, inv);
}

// ---------------------------------------------------------------------------
// Filter kernel: 128 tokens/CTA x 2048 codes via DP4A (exact int32 acc);
// shared per-token running min + candidate append. No calls, no spills.
// ---------------------------------------------------------------------------
__global__ __launch_bounds__(256, 2)
void vq_filter_kernel() {
    __shared__ uint32_t As[8][128];          // [dq][token] int8 quads
    __shared__ uint32_t Bs[8][132];          // [dq][code]
    __shared__ uint32_t sm_m[128];           // per-token shared min (ordered)

    const int tid = threadIdx.x;
    const int tx = tid & 15;
    const int ty = tid >> 4;
    const int n0 = blockIdx.x * 128;

    if (tid < 128) sm_m[tid] = 0xFFFFFFFFu;

    float m_loc[8], zs2[8];
    #pragma unroll
    for (int i = 0; i < 8; i++) {
        m_loc[i] = __int_as_float(0x7f800000);
        zs2[i] = 2.0f * g_zsc[n0 + ty + 16 * i];
    }

    const int a_dq = tid >> 5;
    const int a_tq = (tid & 31) * 4;
    const int b_kk = tid >> 1;
    const int b_p  = (tid & 1) * 4;

    for (int kc = 0; kc < KCB; kc += 128) {
        int acc[8][8];
        #pragma unroll
        for (int i = 0; i < 8; i++)
            #pragma unroll
            for (int j = 0; j < 8; j++) acc[i][j] = 0;

        for (int dq0 = 0; dq0 < 64; dq0 += 8) {
            uint4 av = *(const uint4*)(g_qzp + (size_t)(dq0 + a_dq) * NTOK + n0 + a_tq);
            uint4 bv = *(const uint4*)(g_qc + (size_t)(kc + b_kk) * 64 + dq0 + b_p);
            __syncthreads();
            *(uint4*)&As[a_dq][a_tq] = av;
            Bs[b_p + 0][b_kk] = bv.x;
            Bs[b_p + 1][b_kk] = bv.y;
            Bs[b_p + 2][b_kk] = bv.z;
            Bs[b_p + 3][b_kk] = bv.w;
            __syncthreads();

            #pragma unroll
            for (int dq = 0; dq < 8; dq++) {
                uint32_t a[8], b[8];
                #pragma unroll
                for (int i = 0; i < 8; i++) a[i] = As[dq][ty + 16 * i];
                #pragma unroll
                for (int j = 0; j < 8; j++) b[j] = Bs[dq][tx + 16 * j];
                #pragma unroll
                for (int i = 0; i < 8; i++)
                    #pragma unroll
                    for (int j = 0; j < 8; j++)
                        acc[i][j] = __dp4a((int)a[i], (int)b[j], acc[i][j]);
            }
        }

        // scan: approx score, shared-min update, candidate append
        #pragma unroll
        for (int j = 0; j < 8; j++) {
            const int k = kc + tx + 16 * j;
            const float cs  = g_csc[k];
            const float c2k = g_c2[k];
            #pragma unroll
            for (int i = 0; i < 8; i++) {
                float s = fmaf(-zs2[i] * cs, (float)acc[i][j], c2k);
                if (s < m_loc[i]) {
                    m_loc[i] = s;
                    atomicMin(&sm_m[ty + 16 * i], ordf(s));
                }
                if (s <= m_loc[i] + EPS_SEL) {
                    float msh = unordf(sm_m[ty + 16 * i]);
                    if (s <= msh + EPS_SEL) {
                        int n = n0 + ty + 16 * i;
                        int slot = atomicAdd(&g_ccnt[n], 1);
                        if (slot < CAND) g_cand[(size_t)n * CAND + slot] = k;
                    }
                }
            }
        }
    }
}

// ---------------------------------------------------------------------------
// Rescore kernel: one warp per token; exact fp32 dist (round-7 formula),
// (bits<<32)|k min => first-index tie-break. Overflow -> full scan.
// ---------------------------------------------------------------------------
__global__ __launch_bounds__(256)
void vq_rescore_kernel(const float* __restrict__ cb) {
    const int lane = threadIdx.x & 31;
    const int n = blockIdx.x * 8 + (threadIdx.x >> 5);
    const int cnt = g_ccnt[n];

    unsigned long long key = ~0ULL;
    if (cnt <= CAND) {
        for (int c = lane; c < cnt; c += 32) {
            unsigned long long x = rescore(n, g_cand[(size_t)n * CAND + c], cb);
            if (x < key) key = x;
        }
    } else {
        for (int k = lane; k < KCB; k += 32) {
            unsigned long long x = rescore(n, k, cb);
            if (x < key) key = x;
        }
    }
    #pragma unroll
    for (int off = 16; off; off >>= 1) {
        unsigned long long x = __shfl_xor_sync(0xffffffffu, key, off);
        if (x < key) key = x;
    }
    if (lane == 0) g_idx[n] = (int)(key & 0xFFFFFFFFu);
}

// ---------------------------------------------------------------------------
// Output epilogue: q (straight-through), counts, fused SSE
// ---------------------------------------------------------------------------
__global__ __launch_bounds__(256)
void vq_out_kernel(const float* __restrict__ z, const float* __restrict__ cb,
                   float* __restrict__ out) {
    __shared__ float lred[8];
    const int tid = threadIdx.x;
    const int n0 = blockIdx.x * 128;
    const int b = n0 >> 12, hw0 = n0 & 4095;

    if (tid < 128) atomicAdd(out + QSIZE + 3 + g_idx[n0 + tid], 1.0f);

    const int tok  = tid & 127;
    const int half = tid >> 7;
    const int kidx = g_idx[n0 + tok];
    const float* crow = cb + (size_t)kidx * DD;
    float* qbase = out + (size_t)b * (DD * HW) + hw0 + tok;
    const float* zb2 = z + (size_t)b * (DD * HW) + hw0 + tok;
    float lsum = 0.f;
    #pragma unroll 4
    for (int d = half * 128; d < half * 128 + 128; d++) {
        float c  = crow[d];
        float zz = zb2[(size_t)d * HW];
        float df = zz - c;
        lsum = fmaf(df, df, lsum);
        qbase[(size_t)d * HW] = zz + (c - zz);   // == reference ST rounding
    }
    #pragma unroll
    for (int off = 16; off; off >>= 1) lsum += __shfl_down_sync(0xffffffffu, lsum, off);
    if ((tid & 31) == 0) lred[tid >> 5] = lsum;
    __syncthreads();
    if (tid == 0) {
        float s = 0.f;
        #pragma unroll
        for (int w = 0; w < 8; w++) s += lred[w];
        atomicAdd(out + QSIZE + 1, s);
    }
}

__global__ void finalize_kernel(float* out) {
    float sse = out[QSIZE + 1];
    float mse = sse / (float)((size_t)NTOK * DD);
    out[QSIZE]     = fmaf(0.25f, mse, mse);
    out[QSIZE + 1] = mse;
    out[QSIZE + 2] = mse;
}

// ---------------------------------------------------------------------------
extern "C" void kernel_launch(void* const* d_in, const int* in_sizes, int n_in,
                              void* d_out, int out_size) {
    const float* z  = (const float*)d_in[0];     // (16, 256, 64, 64)
    const float* cb = (const float*)d_in[1];     // (2048, 256)
    float* out = (float*)d_out;

    init_kernel<<<NTOK / 256 + 9, 256>>>(out);
    c2_kernel<<<KCB / 8, 256>>>(cb);
    z2_kernel<<<NTOK / 256, 256>>>(z);
    tz_kernel<<<4096, 256>>>(z);
    qz_kernel<<<64 * NTOK / 256, 256>>>();
    qc_kernel<<<KCB * 64 / 256, 256>>>(cb);
    vq_filter_kernel<<<NTOK / 128, 256>>>();
    vq_rescore_kernel<<<NTOK / 8, 256>>>(cb);
    vq_out_kernel<<<NTOK / 128, 256>>>(z, cb, out);
    finalize_kernel<<<1, 1>>>(out);
}

// round 15
// speedup vs baseline: 52.9145x; 32.1652x over previous
#include <cuda_runtime.h>
#include <cstdint>

// Problem constants
#define DD    256
#define HW    4096
#define NTOK  65536          // 16 * 4096
#define KCB   2048
#define QSIZE 16777216       // 16 * 256 * 4096
// out layout (float32): [0..QSIZE) q, [QSIZE] loss, [QSIZE+1] codebook_loss,
// [QSIZE+2] commitment_loss, [QSIZE+3 .. +KCB) counts

#define EPS_SEL 2.0e-3f      // >= 3x worst-case int8 score error (~6e-4)
#define CAND    32

// Scratch (device globals — no allocs allowed)
__device__ float    g_c2[KCB];
__device__ float    g_csc[KCB];              // cmax/127 (reconstruct scale)
__device__ float    g_z2[NTOK];
__device__ float    g_zsc[NTOK];             // zmax/127
__device__ float    g_zt[(size_t)NTOK * DD]; // z fp32 token-major (64 MB)
__device__ uint32_t g_qzp[64u * NTOK];       // z int8 quads, plane-major (16 MB)
__device__ uint32_t g_qc[(size_t)KCB * 64];  // codebook int8 quads (512 KB)
__device__ int      g_ccnt[NTOK];
__device__ int      g_cand[(size_t)NTOK * CAND];
__device__ int      g_idx[NTOK];

// ---------------------------------------------------------------------------
__device__ __forceinline__ uint32_t pack4(float a, float b, float c, float d,
                                          float inv) {
    int q0 = max(-127, min(127, __float2int_rn(a * inv)));
    int q1 = max(-127, min(127, __float2int_rn(b * inv)));
    int q2 = max(-127, min(127, __float2int_rn(c * inv)));
    int q3 = max(-127, min(127, __float2int_rn(d * inv)));
    return (uint32_t)(q0 & 255) | ((uint32_t)(q1 & 255) << 8) |
           ((uint32_t)(q2 & 255) << 16) | ((uint32_t)q3 << 24);
}

// exact fp32 rescore — byte-identical to rounds 7/14 (argmins == reference)
__device__ __forceinline__ unsigned long long rescore(int n, int k,
                                                      const float* __restrict__ cb) {
    const float4* zp = (const float4*)(g_zt + (size_t)n * DD);
    const float4* cr = (const float4*)(cb + (size_t)k * DD);
    float s0 = 0.f, s1 = 0.f, s2 = 0.f, s3 = 0.f;
    #pragma unroll 8
    for (int i = 0; i < 64; i++) {
        float4 a = zp[i], b = cr[i];
        s0 = fmaf(a.x, b.x, s0); s1 = fmaf(a.y, b.y, s1);
        s2 = fmaf(a.z, b.z, s2); s3 = fmaf(a.w, b.w, s3);
    }
    float dot  = (s0 + s1) + (s2 + s3);
    float dist = fmaf(-2.0f, dot, g_z2[n] + g_c2[k]);
    return ((unsigned long long)__float_as_uint(dist) << 32) | (unsigned)k;
}

// ---------------------------------------------------------------------------
__global__ void init_kernel(float* out) {
    int i = threadIdx.x + blockIdx.x * blockDim.x;
    if (i < 3 + KCB) out[QSIZE + i] = 0.0f;
    if (i < NTOK) g_ccnt[i] = 0;
}

// c2 + per-code max (one warp per code)
__global__ void c2_kernel(const float* __restrict__ cb) {
    int warp = (threadIdx.x >> 5) + blockIdx.x * (blockDim.x >> 5);
    int lane = threadIdx.x & 31;
    if (warp >= KCB) return;
    const float* row = cb + (size_t)warp * DD;
    float s = 0.f, mx = 0.f;
    #pragma unroll
    for (int d = lane; d < DD; d += 32) {
        float v = row[d];
        s = fmaf(v, v, s);
        mx = fmaxf(mx, fabsf(v));
    }
    #pragma unroll
    for (int off = 16; off; off >>= 1) {
        s += __shfl_down_sync(0xffffffffu, s, off);
        mx = fmaxf(mx, __shfl_down_sync(0xffffffffu, mx, off));
    }
    if (lane == 0) {
        g_c2[warp]  = s;
        g_csc[warp] = (mx > 0.f) ? mx * (1.0f / 127.0f) : 1.0f;
    }
}

// z2 + per-token max (sequential fp32 sum — must match reference rounding)
__global__ void z2_kernel(const float* __restrict__ z) {
    int n = threadIdx.x + blockIdx.x * blockDim.x;
    if (n >= NTOK) return;
    int b = n >> 12, hw = n & 4095;
    const float* p = z + (size_t)b * (DD * HW) + hw;
    float s = 0.f, mx = 0.f;
    #pragma unroll 8
    for (int d = 0; d < DD; d++) {
        float v = p[(size_t)d * HW];
        s = fmaf(v, v, s);
        mx = fmaxf(mx, fabsf(v));
    }
    g_z2[n]  = s;
    g_zsc[n] = (mx > 0.f) ? mx * (1.0f / 127.0f) : 1.0f;
}

// transpose z -> token-major fp32 (rescore source + quantization source)
__global__ __launch_bounds__(256)
void tz_kernel(const float* __restrict__ z) {
    __shared__ float t[64][65];
    const int bx = blockIdx.x;
    const int hw0 = (bx & 63) * 64;
    const int d0  = ((bx >> 6) & 3) * 64;
    const int b   = bx >> 8;
    const float* zb = z + (size_t)b * (DD * HW);
    const int tid = threadIdx.x;
    #pragma unroll
    for (int it = 0; it < 16; it++) {
        int p = tid + it * 256;
        int dd = p >> 6, r = p & 63;
        t[dd][r] = zb[(size_t)(d0 + dd) * HW + hw0 + r];
    }
    __syncthreads();
    #pragma unroll
    for (int it = 0; it < 16; it++) {
        int p = tid + it * 256;
        int r = p >> 6, dd = p & 63;
        size_t n = (size_t)b * 4096 + hw0 + r;
        g_zt[n * 256 + d0 + dd] = t[dd][r];
    }
}

// quantize z -> int8 quad planes g_qzp[dq][n]
__global__ void qz_kernel() {
    int idx = threadIdx.x + blockIdx.x * blockDim.x;   // 64 * 65536
    int dq = idx >> 16, n = idx & 65535;
    float inv = 127.0f * __frcp_rn(g_zsc[n] * 127.0f);  // == 1/zsc
    const float4 v = *(const float4*)(g_zt + (size_t)n * 256 + dq * 4);
    g_qzp[(size_t)dq * NTOK + n] = pack4(v.x, v.y, v.z, v.w, inv);
}

// quantize codebook -> int8 quads g_qc[k][64]
__global__ void qc_kernel(const float* __restrict__ cb) {
    int idx = threadIdx.x + blockIdx.x * blockDim.x;   // 2048 * 64
    if (idx >= KCB * 64) return;
    int k = idx >> 6, dq = idx & 63;
    float inv = 127.0f * __frcp_rn(g_csc[k] * 127.0f);
    const float4 v = *(const float4*)(cb + (size_t)k * 256 + dq * 4);
    g_qc[idx] = pack4(v.x, v.y, v.z, v.w, inv);
}

// ---------------------------------------------------------------------------
// Filter kernel: 128 tokens/CTA x 2048 codes via DP4A (exact int32 acc).
// Two-phase chunk epilogue: (1) chunk-wide per-token min via shfl(width=16)
// + smem prefix min, (2) append only codes within EPS of that min.
// ---------------------------------------------------------------------------
__global__ __launch_bounds__(256, 2)
void vq_filter_kernel() {
    __shared__ uint32_t As[8][128];          // [dq][token] int8 quads
    __shared__ uint32_t Bs[8][132];          // [dq][code]
    __shared__ float    sm_min[128];         // per-token prefix min (approx)

    const int tid = threadIdx.x;
    const int tx = tid & 15;
    const int ty = tid >> 4;
    const int n0 = blockIdx.x * 128;

    if (tid < 128) sm_min[tid] = __int_as_float(0x7f800000);

    float zs2[8];
    #pragma unroll
    for (int i = 0; i < 8; i++) zs2[i] = 2.0f * g_zsc[n0 + ty + 16 * i];

    const int a_dq = tid >> 5;
    const int a_tq = (tid & 31) * 4;
    const int b_kk = tid >> 1;
    const int b_p  = (tid & 1) * 4;

    for (int kc = 0; kc < KCB; kc += 128) {
        int acc[8][8];
        #pragma unroll
        for (int i = 0; i < 8; i++)
            #pragma unroll
            for (int j = 0; j < 8; j++) acc[i][j] = 0;

        for (int dq0 = 0; dq0 < 64; dq0 += 8) {
            uint4 av = *(const uint4*)(g_qzp + (size_t)(dq0 + a_dq) * NTOK + n0 + a_tq);
            uint4 bv = *(const uint4*)(g_qc + (size_t)(kc + b_kk) * 64 + dq0 + b_p);
            __syncthreads();
            *(uint4*)&As[a_dq][a_tq] = av;
            Bs[b_p + 0][b_kk] = bv.x;
            Bs[b_p + 1][b_kk] = bv.y;
            Bs[b_p + 2][b_kk] = bv.z;
            Bs[b_p + 3][b_kk] = bv.w;
            __syncthreads();

            #pragma unroll
            for (int dq = 0; dq < 8; dq++) {
                uint32_t a[8], b[8];
                #pragma unroll
                for (int i = 0; i < 8; i++) a[i] = As[dq][ty + 16 * i];
                #pragma unroll
                for (int j = 0; j < 8; j++) b[j] = Bs[dq][tx + 16 * j];
                #pragma unroll
                for (int i = 0; i < 8; i++)
                    #pragma unroll
                    for (int j = 0; j < 8; j++)
                        acc[i][j] = __dp4a((int)a[i], (int)b[j], acc[i][j]);
            }
        }

        // phase 1: scores + chunk-wide per-token min
        float sc[8][8];
        float tmin[8];
        #pragma unroll
        for (int i = 0; i < 8; i++) {
            float mn = __int_as_float(0x7f800000);
            #pragma unroll
            for (int j = 0; j < 8; j++) {
                const int k = kc + tx + 16 * j;
                float s = fmaf(-zs2[i] * g_csc[k], (float)acc[i][j], g_c2[k]);
                sc[i][j] = s;
                mn = fminf(mn, s);
            }
            // min across the 16 lanes sharing this token (half-warp segment)
            #pragma unroll
            for (int off = 1; off < 16; off <<= 1)
                mn = fminf(mn, __shfl_xor_sync(0xffffffffu, mn, off, 16));
            tmin[i] = fminf(mn, sm_min[ty + 16 * i]);
        }

        // phase 2: append candidates within EPS of the prefix+chunk min
        #pragma unroll
        for (int i = 0; i < 8; i++) {
            const float thr = tmin[i] + EPS_SEL;
            #pragma unroll
            for (int j = 0; j < 8; j++) {
                if (sc[i][j] <= thr) {
                    const int n = n0 + ty + 16 * i;
                    int slot = atomicAdd(&g_ccnt[n], 1);
                    if (slot < CAND)
                        g_cand[(size_t)n * CAND + slot] = kc + tx + 16 * j;
                }
            }
            if (tx == 0) sm_min[ty + 16 * i] = tmin[i];   // all lanes agree
        }
    }
}

// ---------------------------------------------------------------------------
// Rescore kernel: one warp per token; exact fp32 dist, (bits<<32)|k min =>
// first-index tie-break. Overflow (cnt > CAND) -> full exact scan.
// ---------------------------------------------------------------------------
__global__ __launch_bounds__(256)
void vq_rescore_kernel(const float* __restrict__ cb) {
    const int lane = threadIdx.x & 31;
    const int n = blockIdx.x * 8 + (threadIdx.x >> 5);
    const int cnt = g_ccnt[n];

    unsigned long long key = ~0ULL;
    if (cnt <= CAND) {
        for (int c = lane; c < cnt; c += 32) {
            unsigned long long x = rescore(n, g_cand[(size_t)n * CAND + c], cb);
            if (x < key) key = x;
        }
    } else {
        for (int k = lane; k < KCB; k += 32) {
            unsigned long long x = rescore(n, k, cb);
            if (x < key) key = x;
        }
    }
    #pragma unroll
    for (int off = 16; off; off >>= 1) {
        unsigned long long x = __shfl_xor_sync(0xffffffffu, key, off);
        if (x < key) key = x;
    }
    if (lane == 0) g_idx[n] = (int)(key & 0xFFFFFFFFu);
}

// ---------------------------------------------------------------------------
// Output epilogue: q (straight-through), counts, fused SSE
// ---------------------------------------------------------------------------
__global__ __launch_bounds__(256)
void vq_out_kernel(const float* __restrict__ z, const float* __restrict__ cb,
                   float* __restrict__ out) {
    __shared__ float lred[8];
    const int tid = threadIdx.x;
    const int n0 = blockIdx.x * 128;
    const int b = n0 >> 12, hw0 = n0 & 4095;

    if (tid < 128) atomicAdd(out + QSIZE + 3 + g_idx[n0 + tid], 1.0f);

    const int tok  = tid & 127;
    const int half = tid >> 7;
    const int kidx = g_idx[n0 + tok];
    const float* crow = cb + (size_t)kidx * DD;
    float* qbase = out + (size_t)b * (DD * HW) + hw0 + tok;
    const float* zb2 = z + (size_t)b * (DD * HW) + hw0 + tok;
    float lsum = 0.f;
    #pragma unroll 4
    for (int d = half * 128; d < half * 128 + 128; d++) {
        float c  = crow[d];
        float zz = zb2[(size_t)d * HW];
        float df = zz - c;
        lsum = fmaf(df, df, lsum);
        qbase[(size_t)d * HW] = zz + (c - zz);   // == reference ST rounding
    }
    #pragma unroll
    for (int off = 16; off; off >>= 1) lsum += __shfl_down_sync(0xffffffffu, lsum, off);
    if ((tid & 31) == 0) lred[tid >> 5] = lsum;
    __syncthreads();
    if (tid == 0) {
        float s = 0.f;
        #pragma unroll
        for (int w = 0; w < 8; w++) s += lred[w];
        atomicAdd(out + QSIZE + 1, s);
    }
}

__global__ void finalize_kernel(float* out) {
    float sse = out[QSIZE + 1];
    float mse = sse / (float)((size_t)NTOK * DD);
    out[QSIZE]     = fmaf(0.25f, mse, mse);
    out[QSIZE + 1] = mse;
    out[QSIZE + 2] = mse;
}

// ---------------------------------------------------------------------------
extern "C" void kernel_launch(void* const* d_in, const int* in_sizes, int n_in,
                              void* d_out, int out_size) {
    const float* z  = (const float*)d_in[0];     // (16, 256, 64, 64)
    const float* cb = (const float*)d_in[1];     // (2048, 256)
    float* out = (float*)d_out;

    init_kernel<<<NTOK / 256 + 9, 256>>>(out);
    c2_kernel<<<KCB / 8, 256>>>(cb);
    z2_kernel<<<NTOK / 256, 256>>>(z);
    tz_kernel<<<4096, 256>>>(z);
    qz_kernel<<<64 * NTOK / 256, 256>>>();
    qc_kernel<<<KCB * 64 / 256, 256>>>(cb);
    vq_filter_kernel<<<NTOK / 128, 256>>>();
    vq_rescore_kernel<<<NTOK / 8, 256>>>(cb);
    vq_out_kernel<<<NTOK / 128, 256>>>(z, cb, out);
    finalize_kernel<<<1, 1>>>(out);
}